// round 10
// baseline (speedup 1.0000x reference)
#include <cuda_runtime.h>
#include <cuda_bf16.h>
#include <cuda_fp8.h>
#include <math.h>
#include <stdint.h>

#define B_ROWS 65536
#define IN_DIM 256
#define G_DIM  512
#define W_DIM  512
#define LN_EPS 1e-5f

// ---------------- global scratch (device globals; no allocs) ----------------
__device__ uint8_t g_x8[(size_t)B_ROWS * IN_DIM];          // inputs e4m3
__device__ uint8_t g_c8[(size_t)G_DIM * IN_DIM];           // centers e4m3
__device__ __nv_bfloat16 g_wb[(size_t)W_DIM * G_DIM];      // W_mix bf16
__device__ __nv_bfloat16 g_scaled[(size_t)B_ROWS * G_DIM]; // RBF activations bf16
__device__ float g_xsq[B_ROWS];
__device__ float g_csq[G_DIM];
__device__ float g_s[G_DIM];
// nonzero flags: [m-tile of 64 rows][K-chunk of 64 cols] for g_scaled
__device__ int g_nz[(B_ROWS / 64) * 8];

// ---------------- PTX helpers (sm_80/89+ subset; compute_103-safe) ----------
__device__ __forceinline__ uint32_t smem_cast(const void* p) {
    return (uint32_t)__cvta_generic_to_shared(p);
}
__device__ __forceinline__ void cp16(uint32_t dst, const void* src) {
    asm volatile("cp.async.cg.shared.global [%0], [%1], 16;" :: "r"(dst), "l"(src));
}
#define CP_COMMIT() asm volatile("cp.async.commit_group;" ::: "memory")
#define CP_WAIT(n)  asm volatile("cp.async.wait_group %0;" :: "n"(n) : "memory")

__device__ __forceinline__ void ldsm4(uint32_t* r, uint32_t addr) {
    asm volatile("ldmatrix.sync.aligned.m8n8.x4.shared.b16 {%0,%1,%2,%3}, [%4];"
                 : "=r"(r[0]), "=r"(r[1]), "=r"(r[2]), "=r"(r[3]) : "r"(addr));
}
__device__ __forceinline__ void mma_bf16(float* d, const uint32_t* a,
                                         uint32_t b0, uint32_t b1) {
    asm volatile(
        "mma.sync.aligned.m16n8k16.row.col.f32.bf16.bf16.f32 "
        "{%0,%1,%2,%3}, {%4,%5,%6,%7}, {%8,%9}, {%0,%1,%2,%3};"
        : "+f"(d[0]), "+f"(d[1]), "+f"(d[2]), "+f"(d[3])
        : "r"(a[0]), "r"(a[1]), "r"(a[2]), "r"(a[3]), "r"(b0), "r"(b1));
}
__device__ __forceinline__ void mma_fp8(float* d, const uint32_t* a,
                                        uint32_t b0, uint32_t b1) {
    asm volatile(
        "mma.sync.aligned.m16n8k32.row.col.f32.e4m3.e4m3.f32 "
        "{%0,%1,%2,%3}, {%4,%5,%6,%7}, {%8,%9}, {%0,%1,%2,%3};"
        : "+f"(d[0]), "+f"(d[1]), "+f"(d[2]), "+f"(d[3])
        : "r"(a[0]), "r"(a[1]), "r"(a[2]), "r"(a[3]), "r"(b0), "r"(b1));
}

__device__ __forceinline__ ushort4 cvt8_e4m3(float4 a0, float4 a1) {
    ushort4 u;
    u.x = __nv_cvt_float2_to_fp8x2(make_float2(a0.x, a0.y), __NV_SATFINITE, __NV_E4M3);
    u.y = __nv_cvt_float2_to_fp8x2(make_float2(a0.z, a0.w), __NV_SATFINITE, __NV_E4M3);
    u.z = __nv_cvt_float2_to_fp8x2(make_float2(a1.x, a1.y), __NV_SATFINITE, __NV_E4M3);
    u.w = __nv_cvt_float2_to_fp8x2(make_float2(a1.z, a1.w), __NV_SATFINITE, __NV_E4M3);
    return u;
}

// fast tanh: 1 - 2/(e^{2x}+1). <= ~1e-6 rel err; saturates cleanly at +-1.
__device__ __forceinline__ float ftanh(float x) {
    float t = __expf(2.0f * x);
    return 1.0f - __fdividef(2.0f, t + 1.0f);
}

// ---------------- prep kernels ----------------------------------------------
__global__ __launch_bounds__(256) void conv_x(const float* __restrict__ x) {
    int row = blockIdx.x * 8 + (threadIdx.x >> 5);
    int lane = threadIdx.x & 31;
    const float* r = x + (size_t)row * IN_DIM;
    int k0 = lane * 8;
    float4 a0 = *(const float4*)(r + k0);
    float4 a1 = *(const float4*)(r + k0 + 4);
    float ss = a0.x*a0.x + a0.y*a0.y + a0.z*a0.z + a0.w*a0.w +
               a1.x*a1.x + a1.y*a1.y + a1.z*a1.z + a1.w*a1.w;
#pragma unroll
    for (int o = 16; o > 0; o >>= 1) ss += __shfl_xor_sync(0xffffffffu, ss, o);
    if (lane == 0) g_xsq[row] = ss;
    *(ushort4*)(g_x8 + (size_t)row * IN_DIM + k0) = cvt8_e4m3(a0, a1);
}

__global__ __launch_bounds__(256) void conv_cw(const float* __restrict__ c,
                                               const float* __restrict__ ls,
                                               const float* __restrict__ w) {
    const int gtid = blockIdx.x * 256 + threadIdx.x;
    if (gtid < (B_ROWS / 64) * 8) g_nz[gtid] = 0;

    int lane = threadIdx.x & 31;
    if (blockIdx.x < 64) {
        int g = blockIdx.x * 8 + (threadIdx.x >> 5);
        const float* r = c + (size_t)g * IN_DIM;
        int k0 = lane * 8;
        float4 a0 = *(const float4*)(r + k0);
        float4 a1 = *(const float4*)(r + k0 + 4);
        float ss = a0.x*a0.x + a0.y*a0.y + a0.z*a0.z + a0.w*a0.w +
                   a1.x*a1.x + a1.y*a1.y + a1.z*a1.z + a1.w*a1.w;
#pragma unroll
        for (int o = 16; o > 0; o >>= 1) ss += __shfl_xor_sync(0xffffffffu, ss, o);
        if (lane == 0) { g_csq[g] = ss; g_s[g] = expf(ls[g]); }
        *(ushort4*)(g_c8 + (size_t)g * IN_DIM + k0) = cvt8_e4m3(a0, a1);
    } else {
        int wr = (blockIdx.x - 64) * 8 + (threadIdx.x >> 5);
        const float* r = w + (size_t)wr * G_DIM;
#pragma unroll
        for (int part = 0; part < 2; part++) {
            int k0 = lane * 16 + part * 8;
            float4 a0 = *(const float4*)(r + k0);
            float4 a1 = *(const float4*)(r + k0 + 4);
            __nv_bfloat162 h0 = __floats2bfloat162_rn(a0.x, a0.y);
            __nv_bfloat162 h1 = __floats2bfloat162_rn(a0.z, a0.w);
            __nv_bfloat162 h2 = __floats2bfloat162_rn(a1.x, a1.y);
            __nv_bfloat162 h3 = __floats2bfloat162_rn(a1.z, a1.w);
            *(uint4*)(g_wb + (size_t)wr * G_DIM + k0) =
                make_uint4(*(uint32_t*)&h0, *(uint32_t*)&h1, *(uint32_t*)&h2, *(uint32_t*)&h3);
        }
    }
}

// ---------------- GEMM1 (RBF, e4m3): 128x128 tile, K=256 resident ------------
#define P1 272
#define G1_B   (128 * P1)
#define G1_SMEM (2 * 128 * P1 + 1024)

__global__ __launch_bounds__(256, 2) void gemm1_rbf() {
    extern __shared__ __align__(16) uint8_t sm[];
    float* s_c0 = (float*)(sm + 2 * 128 * P1);
    float* s_c1 = s_c0 + 128;

    const int tid = threadIdx.x, lane = tid & 31, wid = tid >> 5;
    const int bm = blockIdx.y * 128, bn = blockIdx.x * 128;

    if (tid < 128) { s_c0[tid] = g_csq[bn + tid]; s_c1[tid] = g_s[bn + tid]; }

    const uint32_t sbase = smem_cast(sm);
#pragma unroll
    for (int i = 0; i < 8; i++) {
        const int v = i * 256 + tid;
        const int row = v >> 4, cb = (v & 15) * 16;
        cp16(sbase + (uint32_t)(row * P1 + cb), g_x8 + (size_t)(bm + row) * IN_DIM + cb);
    }
#pragma unroll
    for (int i = 0; i < 8; i++) {
        const int v = i * 256 + tid;
        const int row = v >> 4, cb = (v & 15) * 16;
        cp16(sbase + (uint32_t)(G1_B + row * P1 + cb), g_c8 + (size_t)(bn + row) * IN_DIM + cb);
    }
    CP_COMMIT();
    CP_WAIT(0);
    __syncthreads();

    const int m0 = (wid >> 2) * 64, n0 = (wid & 3) * 32;
    const int arow = lane & 15, acolb = (lane >> 4) * 16;
    const int brow = (lane & 7) | ((lane & 16) >> 1), bcolb = (lane & 8) * 2;

    float acc[4][4][4] = {};
    uint32_t af[2][4][4], bfr[2][2][4];

    auto load_frags = [&](int kk, int b) {
#pragma unroll
        for (int mf = 0; mf < 4; mf++)
            ldsm4(af[b][mf], sbase + (uint32_t)((m0 + mf * 16 + arow) * P1 + kk * 32 + acolb));
#pragma unroll
        for (int nh = 0; nh < 2; nh++)
            ldsm4(bfr[b][nh], sbase + (uint32_t)(G1_B + (n0 + nh * 16 + brow) * P1 + kk * 32 + bcolb));
    };
    auto do_mma = [&](int b) {
#pragma unroll
        for (int mf = 0; mf < 4; mf++)
#pragma unroll
            for (int nf = 0; nf < 4; nf++)
                mma_fp8(acc[mf][nf], af[b][mf],
                        bfr[b][nf >> 1][(nf & 1) * 2], bfr[b][nf >> 1][(nf & 1) * 2 + 1]);
    };

    load_frags(0, 0);
#pragma unroll
    for (int kk = 0; kk < 8; kk++) {
        if (kk < 7) load_frags(kk + 1, (kk + 1) & 1);
        do_mma(kk & 1);
    }

    // epilogue: exp(-(xq+cq-2acc)*s) -> g_scaled bf16 (predicated stores) + flags
    const int erow = lane >> 2, ecol = (lane & 3) * 2;
    uint32_t nzu = 0;
#pragma unroll
    for (int mf = 0; mf < 4; mf++) {
        const int gm0 = bm + m0 + mf * 16 + erow;
        const float xq0 = g_xsq[gm0], xq1 = g_xsq[gm0 + 8];
#pragma unroll
        for (int nf = 0; nf < 4; nf++) {
            const int cl = n0 + nf * 8 + ecol;
            const int gc = bn + cl;
            const float cq0 = s_c0[cl], ss0 = s_c1[cl];
            const float cq1 = s_c0[cl + 1], ss1 = s_c1[cl + 1];
            float v00 = __expf((2.f * acc[mf][nf][0] - xq0 - cq0) * ss0);
            float v01 = __expf((2.f * acc[mf][nf][1] - xq0 - cq1) * ss1);
            float v10 = __expf((2.f * acc[mf][nf][2] - xq1 - cq0) * ss0);
            float v11 = __expf((2.f * acc[mf][nf][3] - xq1 - cq1) * ss1);
            __nv_bfloat162 h0 = __floats2bfloat162_rn(v00, v01);
            __nv_bfloat162 h1 = __floats2bfloat162_rn(v10, v11);
            const uint32_t p0 = *(uint32_t*)&h0, p1 = *(uint32_t*)&h1;
            nzu |= p0 | p1;
            if (p0) *(uint32_t*)(g_scaled + (size_t)gm0 * G_DIM + gc) = p0;
            if (p1) *(uint32_t*)(g_scaled + (size_t)(gm0 + 8) * G_DIM + gc) = p1;
        }
    }
    const uint32_t any = __reduce_or_sync(0xffffffffu, nzu);
    if (lane == 0 && any)
        atomicOr(&g_nz[((bm + m0) >> 6) * 8 + ((bn + n0) >> 6)], 1);
}

// ---------------- GEMM2 + LayerNorm + tanh: 64x512 CTA, 512 thr, BK=64 -------
#define G2P 72
#define G2_STG (576 * G2P)
#define G2_FLT ((size_t)(2 * G2_STG) * 2)
#define G2_SMEM (G2_FLT + (512 * 3 + 64 * 8 * 2 + 128 + 8) * 4)

__global__ __launch_bounds__(512, 1) void gemm2_ln(const float* __restrict__ bias,
                                                   const float* __restrict__ gamma,
                                                   const float* __restrict__ beta,
                                                   float* __restrict__ out) {
    extern __shared__ __align__(16) __nv_bfloat16 smh[];
    float* vs_b  = (float*)((char*)smh + G2_FLT);
    float* vs_g  = vs_b + 512;
    float* vs_be = vs_g + 512;
    float* part_sum = vs_be + 512;   // [64 rows][8 col-groups]
    float* part_sq  = part_sum + 512;
    float* stats    = part_sq + 512; // [64][2] mean,rstd
    int*   s_nz     = (int*)(stats + 128);

    const int tid = threadIdx.x, lane = tid & 31, wid = tid >> 5;
    const int bm = blockIdx.x * 64;

    if (tid < 512) { vs_b[tid] = bias[tid]; vs_g[tid] = gamma[tid]; vs_be[tid] = beta[tid]; }
    if (tid < 8) s_nz[tid] = g_nz[(bm >> 6) * 8 + tid];
    __syncthreads();

    int act[8], nact = 0;
#pragma unroll
    for (int k = 0; k < 8; k++) if (s_nz[k]) act[nact++] = k;

    const uint32_t sb0 = smem_cast(smh);
    const int crow = tid >> 3, cc8 = (tid & 7) * 8;

    auto load_chunk = [&](int kc, int stg) {
        const uint32_t base = sb0 + (uint32_t)(stg * G2_STG) * 2;
        cp16(base + (uint32_t)(crow * G2P + cc8) * 2,
             g_scaled + (size_t)(bm + crow) * G_DIM + kc * 64 + cc8);
#pragma unroll
        for (int i = 0; i < 8; i++) {
            const int r = crow + i * 64;
            cp16(base + (uint32_t)((64 + r) * G2P + cc8) * 2,
                 g_wb + (size_t)r * G_DIM + kc * 64 + cc8);
        }
    };

    const int wr = wid >> 3, wc = wid & 7;
    const int arow = lane & 15, acol = (lane >> 4) << 3;
    const int brow = (lane & 7) | ((lane & 16) >> 1), bcol = lane & 8;

    float acc[2][8][4] = {};

    if (nact > 0) {
        load_chunk(act[0], 0); CP_COMMIT();
        if (nact > 1) { load_chunk(act[1], 1); CP_COMMIT(); }

#pragma unroll 1
        for (int i = 0; i < nact; i++) {
            if (i + 1 < nact) { CP_WAIT(1); } else { CP_WAIT(0); }
            __syncthreads();
            const uint32_t base = sb0 + (uint32_t)((i & 1) * G2_STG) * 2;
#pragma unroll
            for (int kk = 0; kk < 4; kk++) {
                uint32_t af[2][4], bfr[4][4];
#pragma unroll
                for (int mf = 0; mf < 2; mf++)
                    ldsm4(af[mf], base + (uint32_t)((wr * 32 + mf * 16 + arow) * G2P +
                                                    kk * 16 + acol) * 2);
#pragma unroll
                for (int nh = 0; nh < 4; nh++)
                    ldsm4(bfr[nh], base + (uint32_t)((64 + wc * 64 + nh * 16 + brow) * G2P +
                                                     kk * 16 + bcol) * 2);
#pragma unroll
                for (int mf = 0; mf < 2; mf++)
#pragma unroll
                    for (int nf = 0; nf < 8; nf++)
                        mma_bf16(acc[mf][nf], af[mf],
                                 bfr[nf >> 1][(nf & 1) * 2], bfr[nf >> 1][(nf & 1) * 2 + 1]);
            }
            __syncthreads();
            if (i + 2 < nact) { load_chunk(act[i + 2], i & 1); CP_COMMIT(); }
        }
    }

    // ----- LayerNorm + tanh epilogue (fp32) -----
    const int ecol = (lane & 3) * 2;
#pragma unroll
    for (int mf = 0; mf < 2; mf++) {
        float s0 = 0.f, q0 = 0.f, s1 = 0.f, q1 = 0.f;
#pragma unroll
        for (int nf = 0; nf < 8; nf++) {
            const int c = wc * 64 + nf * 8 + ecol;
            float v00 = acc[mf][nf][0] + vs_b[c];
            float v01 = acc[mf][nf][1] + vs_b[c + 1];
            float v10 = acc[mf][nf][2] + vs_b[c];
            float v11 = acc[mf][nf][3] + vs_b[c + 1];
            acc[mf][nf][0] = v00; acc[mf][nf][1] = v01;
            acc[mf][nf][2] = v10; acc[mf][nf][3] = v11;
            s0 += v00 + v01; q0 += v00 * v00 + v01 * v01;
            s1 += v10 + v11; q1 += v10 * v10 + v11 * v11;
        }
#pragma unroll
        for (int o = 1; o <= 2; o <<= 1) {
            s0 += __shfl_xor_sync(0xffffffffu, s0, o);
            q0 += __shfl_xor_sync(0xffffffffu, q0, o);
            s1 += __shfl_xor_sync(0xffffffffu, s1, o);
            q1 += __shfl_xor_sync(0xffffffffu, q1, o);
        }
        if ((lane & 3) == 0) {
            const int r0 = wr * 32 + mf * 16 + (lane >> 2);
            part_sum[r0 * 8 + wc] = s0;       part_sq[r0 * 8 + wc] = q0;
            part_sum[(r0 + 8) * 8 + wc] = s1; part_sq[(r0 + 8) * 8 + wc] = q1;
        }
    }
    __syncthreads();
    if (tid < 64) {
        float s = 0.f, q = 0.f;
#pragma unroll
        for (int w = 0; w < 8; w++) { s += part_sum[tid * 8 + w]; q += part_sq[tid * 8 + w]; }
        const float mean = s * (1.0f / 512.0f);
        const float var  = q * (1.0f / 512.0f) - mean * mean;
        stats[tid * 2] = mean;
        stats[tid * 2 + 1] = rsqrtf(var + LN_EPS);
    }
    __syncthreads();

#pragma unroll
    for (int mf = 0; mf < 2; mf++) {
        const int r0 = wr * 32 + mf * 16 + (lane >> 2), r1 = r0 + 8;
        const float m0 = stats[r0 * 2], rs0 = stats[r0 * 2 + 1];
        const float m1 = stats[r1 * 2], rs1 = stats[r1 * 2 + 1];
#pragma unroll
        for (int nf = 0; nf < 8; nf++) {
            const int c = wc * 64 + nf * 8 + ecol;
            const float g0 = vs_g[c], g1 = vs_g[c + 1];
            const float be0 = vs_be[c], be1 = vs_be[c + 1];
            float2 y0 = make_float2(ftanh((acc[mf][nf][0] - m0) * rs0 * g0 + be0),
                                    ftanh((acc[mf][nf][1] - m0) * rs0 * g1 + be1));
            float2 y1 = make_float2(ftanh((acc[mf][nf][2] - m1) * rs1 * g0 + be0),
                                    ftanh((acc[mf][nf][3] - m1) * rs1 * g1 + be1));
            *(float2*)(out + (size_t)(bm + r0) * W_DIM + c) = y0;
            *(float2*)(out + (size_t)(bm + r1) * W_DIM + c) = y1;
        }
    }
}

// ---------------------------------------------------------------------------
extern "C" void kernel_launch(void* const* d_in, const int* in_sizes, int n_in,
                              void* d_out, int out_size) {
    const float* inputs     = (const float*)d_in[0];
    const float* centers    = (const float*)d_in[1];
    const float* log_scales = (const float*)d_in[2];
    const float* W_mix      = (const float*)d_in[3];
    const float* b_mix      = (const float*)d_in[4];
    const float* ln_gamma   = (const float*)d_in[5];
    const float* ln_beta    = (const float*)d_in[6];
    float* out = (float*)d_out;

    cudaFuncSetAttribute(gemm1_rbf, cudaFuncAttributeMaxDynamicSharedMemorySize, G1_SMEM);
    cudaFuncSetAttribute(gemm2_ln,  cudaFuncAttributeMaxDynamicSharedMemorySize, (int)G2_SMEM);

    conv_x<<<B_ROWS / 8, 256>>>(inputs);
    conv_cw<<<128, 256>>>(centers, log_scales, W_mix);
    gemm1_rbf<<<dim3(G_DIM / 128, B_ROWS / 128), 256, G1_SMEM>>>();
    gemm2_ln<<<B_ROWS / 64, 512, G2_SMEM>>>(b_mix, ln_gamma, ln_beta, out);
}

// round 11
// speedup vs baseline: 1.1123x; 1.1123x over previous
#include <cuda_runtime.h>
#include <cuda_bf16.h>
#include <cuda_fp8.h>
#include <math.h>
#include <stdint.h>

#define B_ROWS 65536
#define IN_DIM 256
#define G_DIM  512
#define W_DIM  512
#define LN_EPS 1e-5f

// ---------------- global scratch (device globals; no allocs) ----------------
__device__ uint8_t g_x8[(size_t)B_ROWS * IN_DIM];          // inputs e4m3
__device__ uint8_t g_c8[(size_t)G_DIM * IN_DIM];           // centers e4m3
__device__ __nv_bfloat16 g_wb[(size_t)W_DIM * G_DIM];      // W_mix bf16
__device__ __nv_bfloat16 g_scaled[(size_t)B_ROWS * G_DIM]; // RBF activations bf16
__device__ float g_xsq[B_ROWS];
__device__ float g_csq[G_DIM];
__device__ float g_s[G_DIM];
// nonzero flags: [m-tile of 64 rows][K-chunk of 64 cols] for g_scaled
__device__ int g_nz[(B_ROWS / 64) * 8];

// ---------------- PTX helpers (sm_80/89+ subset; compute_103-safe) ----------
__device__ __forceinline__ uint32_t smem_cast(const void* p) {
    return (uint32_t)__cvta_generic_to_shared(p);
}
__device__ __forceinline__ void cp16(uint32_t dst, const void* src) {
    asm volatile("cp.async.cg.shared.global [%0], [%1], 16;" :: "r"(dst), "l"(src));
}
#define CP_COMMIT() asm volatile("cp.async.commit_group;" ::: "memory")
#define CP_WAIT(n)  asm volatile("cp.async.wait_group %0;" :: "n"(n) : "memory")

__device__ __forceinline__ void ldsm4(uint32_t* r, uint32_t addr) {
    asm volatile("ldmatrix.sync.aligned.m8n8.x4.shared.b16 {%0,%1,%2,%3}, [%4];"
                 : "=r"(r[0]), "=r"(r[1]), "=r"(r[2]), "=r"(r[3]) : "r"(addr));
}
__device__ __forceinline__ void mma_bf16(float* d, const uint32_t* a,
                                         uint32_t b0, uint32_t b1) {
    asm volatile(
        "mma.sync.aligned.m16n8k16.row.col.f32.bf16.bf16.f32 "
        "{%0,%1,%2,%3}, {%4,%5,%6,%7}, {%8,%9}, {%0,%1,%2,%3};"
        : "+f"(d[0]), "+f"(d[1]), "+f"(d[2]), "+f"(d[3])
        : "r"(a[0]), "r"(a[1]), "r"(a[2]), "r"(a[3]), "r"(b0), "r"(b1));
}
__device__ __forceinline__ void mma_fp8(float* d, const uint32_t* a,
                                        uint32_t b0, uint32_t b1) {
    asm volatile(
        "mma.sync.aligned.m16n8k32.row.col.f32.e4m3.e4m3.f32 "
        "{%0,%1,%2,%3}, {%4,%5,%6,%7}, {%8,%9}, {%0,%1,%2,%3};"
        : "+f"(d[0]), "+f"(d[1]), "+f"(d[2]), "+f"(d[3])
        : "r"(a[0]), "r"(a[1]), "r"(a[2]), "r"(a[3]), "r"(b0), "r"(b1));
}

__device__ __forceinline__ ushort4 cvt8_e4m3(float4 a0, float4 a1) {
    ushort4 u;
    u.x = __nv_cvt_float2_to_fp8x2(make_float2(a0.x, a0.y), __NV_SATFINITE, __NV_E4M3);
    u.y = __nv_cvt_float2_to_fp8x2(make_float2(a0.z, a0.w), __NV_SATFINITE, __NV_E4M3);
    u.z = __nv_cvt_float2_to_fp8x2(make_float2(a1.x, a1.y), __NV_SATFINITE, __NV_E4M3);
    u.w = __nv_cvt_float2_to_fp8x2(make_float2(a1.z, a1.w), __NV_SATFINITE, __NV_E4M3);
    return u;
}

// ---------------- prep kernels ----------------------------------------------
__global__ __launch_bounds__(256) void conv_x(const float* __restrict__ x) {
    int row = blockIdx.x * 8 + (threadIdx.x >> 5);
    int lane = threadIdx.x & 31;
    const float* r = x + (size_t)row * IN_DIM;
    int k0 = lane * 8;
    float4 a0 = *(const float4*)(r + k0);
    float4 a1 = *(const float4*)(r + k0 + 4);
    float ss = a0.x*a0.x + a0.y*a0.y + a0.z*a0.z + a0.w*a0.w +
               a1.x*a1.x + a1.y*a1.y + a1.z*a1.z + a1.w*a1.w;
#pragma unroll
    for (int o = 16; o > 0; o >>= 1) ss += __shfl_xor_sync(0xffffffffu, ss, o);
    if (lane == 0) g_xsq[row] = ss;
    *(ushort4*)(g_x8 + (size_t)row * IN_DIM + k0) = cvt8_e4m3(a0, a1);
}

__global__ __launch_bounds__(256) void conv_cw(const float* __restrict__ c,
                                               const float* __restrict__ ls,
                                               const float* __restrict__ w) {
    const int gtid = blockIdx.x * 256 + threadIdx.x;
    if (gtid < (B_ROWS / 64) * 8) g_nz[gtid] = 0;

    int lane = threadIdx.x & 31;
    if (blockIdx.x < 64) {
        int g = blockIdx.x * 8 + (threadIdx.x >> 5);
        const float* r = c + (size_t)g * IN_DIM;
        int k0 = lane * 8;
        float4 a0 = *(const float4*)(r + k0);
        float4 a1 = *(const float4*)(r + k0 + 4);
        float ss = a0.x*a0.x + a0.y*a0.y + a0.z*a0.z + a0.w*a0.w +
                   a1.x*a1.x + a1.y*a1.y + a1.z*a1.z + a1.w*a1.w;
#pragma unroll
        for (int o = 16; o > 0; o >>= 1) ss += __shfl_xor_sync(0xffffffffu, ss, o);
        if (lane == 0) { g_csq[g] = ss; g_s[g] = expf(ls[g]); }
        *(ushort4*)(g_c8 + (size_t)g * IN_DIM + k0) = cvt8_e4m3(a0, a1);
    } else {
        int wr = (blockIdx.x - 64) * 8 + (threadIdx.x >> 5);
        const float* r = w + (size_t)wr * G_DIM;
#pragma unroll
        for (int part = 0; part < 2; part++) {
            int k0 = lane * 16 + part * 8;
            float4 a0 = *(const float4*)(r + k0);
            float4 a1 = *(const float4*)(r + k0 + 4);
            __nv_bfloat162 h0 = __floats2bfloat162_rn(a0.x, a0.y);
            __nv_bfloat162 h1 = __floats2bfloat162_rn(a0.z, a0.w);
            __nv_bfloat162 h2 = __floats2bfloat162_rn(a1.x, a1.y);
            __nv_bfloat162 h3 = __floats2bfloat162_rn(a1.z, a1.w);
            *(uint4*)(g_wb + (size_t)wr * G_DIM + k0) =
                make_uint4(*(uint32_t*)&h0, *(uint32_t*)&h1, *(uint32_t*)&h2, *(uint32_t*)&h3);
        }
    }
}

// ---------------- GEMM1 (RBF, e4m3): 128x128 tile, K=256 resident ------------
#define P1 272
#define G1_B   (128 * P1)
#define G1_SMEM (2 * 128 * P1 + 1024)

__global__ __launch_bounds__(256, 2) void gemm1_rbf() {
    extern __shared__ __align__(16) uint8_t sm[];
    float* s_c0 = (float*)(sm + 2 * 128 * P1);
    float* s_c1 = s_c0 + 128;

    const int tid = threadIdx.x, lane = tid & 31, wid = tid >> 5;
    const int bm = blockIdx.y * 128, bn = blockIdx.x * 128;

    if (tid < 128) { s_c0[tid] = g_csq[bn + tid]; s_c1[tid] = g_s[bn + tid]; }

    const uint32_t sbase = smem_cast(sm);
#pragma unroll
    for (int i = 0; i < 8; i++) {
        const int v = i * 256 + tid;
        const int row = v >> 4, cb = (v & 15) * 16;
        cp16(sbase + (uint32_t)(row * P1 + cb), g_x8 + (size_t)(bm + row) * IN_DIM + cb);
    }
#pragma unroll
    for (int i = 0; i < 8; i++) {
        const int v = i * 256 + tid;
        const int row = v >> 4, cb = (v & 15) * 16;
        cp16(sbase + (uint32_t)(G1_B + row * P1 + cb), g_c8 + (size_t)(bn + row) * IN_DIM + cb);
    }
    CP_COMMIT();
    CP_WAIT(0);
    __syncthreads();

    const int m0 = (wid >> 2) * 64, n0 = (wid & 3) * 32;
    const int arow = lane & 15, acolb = (lane >> 4) * 16;
    const int brow = (lane & 7) | ((lane & 16) >> 1), bcolb = (lane & 8) * 2;

    float acc[4][4][4] = {};
    uint32_t af[2][4][4], bfr[2][2][4];

    auto load_frags = [&](int kk, int b) {
#pragma unroll
        for (int mf = 0; mf < 4; mf++)
            ldsm4(af[b][mf], sbase + (uint32_t)((m0 + mf * 16 + arow) * P1 + kk * 32 + acolb));
#pragma unroll
        for (int nh = 0; nh < 2; nh++)
            ldsm4(bfr[b][nh], sbase + (uint32_t)(G1_B + (n0 + nh * 16 + brow) * P1 + kk * 32 + bcolb));
    };
    auto do_mma = [&](int b) {
#pragma unroll
        for (int mf = 0; mf < 4; mf++)
#pragma unroll
            for (int nf = 0; nf < 4; nf++)
                mma_fp8(acc[mf][nf], af[b][mf],
                        bfr[b][nf >> 1][(nf & 1) * 2], bfr[b][nf >> 1][(nf & 1) * 2 + 1]);
    };

    load_frags(0, 0);
#pragma unroll
    for (int kk = 0; kk < 8; kk++) {
        if (kk < 7) load_frags(kk + 1, (kk + 1) & 1);
        do_mma(kk & 1);
    }

    // epilogue: exp(-(xq+cq-2acc)*s) -> g_scaled bf16 (predicated stores) + flags
    const int erow = lane >> 2, ecol = (lane & 3) * 2;
    uint32_t nzu = 0;
#pragma unroll
    for (int mf = 0; mf < 4; mf++) {
        const int gm0 = bm + m0 + mf * 16 + erow;
        const float xq0 = g_xsq[gm0], xq1 = g_xsq[gm0 + 8];
#pragma unroll
        for (int nf = 0; nf < 4; nf++) {
            const int cl = n0 + nf * 8 + ecol;
            const int gc = bn + cl;
            const float cq0 = s_c0[cl], ss0 = s_c1[cl];
            const float cq1 = s_c0[cl + 1], ss1 = s_c1[cl + 1];
            float v00 = __expf((2.f * acc[mf][nf][0] - xq0 - cq0) * ss0);
            float v01 = __expf((2.f * acc[mf][nf][1] - xq0 - cq1) * ss1);
            float v10 = __expf((2.f * acc[mf][nf][2] - xq1 - cq0) * ss0);
            float v11 = __expf((2.f * acc[mf][nf][3] - xq1 - cq1) * ss1);
            __nv_bfloat162 h0 = __floats2bfloat162_rn(v00, v01);
            __nv_bfloat162 h1 = __floats2bfloat162_rn(v10, v11);
            const uint32_t p0 = *(uint32_t*)&h0, p1 = *(uint32_t*)&h1;
            nzu |= p0 | p1;
            if (p0) *(uint32_t*)(g_scaled + (size_t)gm0 * G_DIM + gc) = p0;
            if (p1) *(uint32_t*)(g_scaled + (size_t)(gm0 + 8) * G_DIM + gc) = p1;
        }
    }
    const uint32_t any = __reduce_or_sync(0xffffffffu, nzu);
    if (lane == 0 && any)
        atomicOr(&g_nz[((bm + m0) >> 6) * 8 + ((bn + n0) >> 6)], 1);
}

// ---------------- GEMM2 + LayerNorm + tanh: 64x512 CTA, 512 thr, BK=64 -------
// Block-sparse over K. Fast path: tile with zero active chunks -> expanded
// equals bias for every row -> one shared LN+tanh vector, broadcast stores.
#define G2P 72
#define G2_STG (576 * G2P)
#define G2_FLT ((size_t)(2 * G2_STG) * 2)
#define G2_SMEM (G2_FLT + (512 * 4 + 64 * 8 * 2 + 128 + 8 + 64) * 4)

__global__ __launch_bounds__(512, 1) void gemm2_ln(const float* __restrict__ bias,
                                                   const float* __restrict__ gamma,
                                                   const float* __restrict__ beta,
                                                   float* __restrict__ out) {
    extern __shared__ __align__(16) __nv_bfloat16 smh[];
    float* vs_b  = (float*)((char*)smh + G2_FLT);
    float* vs_g  = vs_b + 512;
    float* vs_be = vs_g + 512;
    float* ybuf  = vs_be + 512;      // fast-path result vector (512)
    float* part_sum = ybuf + 512;    // [64 rows][8 col-groups]
    float* part_sq  = part_sum + 512;
    float* stats    = part_sq + 512; // [64][2] mean,rstd
    int*   s_nz     = (int*)(stats + 128);
    float* red      = (float*)(s_nz + 8);   // 32 floats cross-warp reduce

    const int tid = threadIdx.x, lane = tid & 31, wid = tid >> 5;
    const int bm = blockIdx.x * 64;

    vs_b[tid] = bias[tid]; vs_g[tid] = gamma[tid]; vs_be[tid] = beta[tid];
    if (tid < 8) s_nz[tid] = g_nz[(bm >> 6) * 8 + tid];
    __syncthreads();

    int act[8], nact = 0;
#pragma unroll
    for (int k = 0; k < 8; k++) if (s_nz[k]) act[nact++] = k;

    // ================= FAST PATH: all chunks zero =================
    if (nact == 0) {
        // LN+tanh of the bias vector, computed once (thread tid <-> column tid)
        const float v = vs_b[tid];
        float s = v, q = v * v;
#pragma unroll
        for (int o = 16; o > 0; o >>= 1) {
            s += __shfl_xor_sync(0xffffffffu, s, o);
            q += __shfl_xor_sync(0xffffffffu, q, o);
        }
        if (lane == 0) { red[wid] = s; red[wid + 16] = q; }
        __syncthreads();
        if (tid == 0) {
            float ts = 0.f, tq = 0.f;
#pragma unroll
            for (int w = 0; w < 16; w++) { ts += red[w]; tq += red[w + 16]; }
            const float mean = ts * (1.0f / 512.0f);
            const float var  = tq * (1.0f / 512.0f) - mean * mean;
            red[0] = mean;
            red[1] = rsqrtf(var + LN_EPS);
        }
        __syncthreads();
        const float mean = red[0], rstd = red[1];
        ybuf[tid] = tanhf((v - mean) * rstd * vs_g[tid] + vs_be[tid]);
        __syncthreads();

        // broadcast-store 64 rows x 512 cols (float4)
        const float4* y4 = (const float4*)ybuf;
        float4* o4 = (float4*)(out + (size_t)bm * W_DIM);
#pragma unroll
        for (int i = 0; i < 16; i++) {
            const int idx = tid + i * 512;          // 0..8191
            const int col = idx & 127;              // 128 float4 per row
            o4[idx] = y4[col];
        }
        return;
    }

    // ================= SLOW PATH: general block-sparse GEMM + LN =============
    const uint32_t sb0 = smem_cast(smh);
    const int crow = tid >> 3, cc8 = (tid & 7) * 8;

    auto load_chunk = [&](int kc, int stg) {
        const uint32_t base = sb0 + (uint32_t)(stg * G2_STG) * 2;
        cp16(base + (uint32_t)(crow * G2P + cc8) * 2,
             g_scaled + (size_t)(bm + crow) * G_DIM + kc * 64 + cc8);
#pragma unroll
        for (int i = 0; i < 8; i++) {
            const int r = crow + i * 64;
            cp16(base + (uint32_t)((64 + r) * G2P + cc8) * 2,
                 g_wb + (size_t)r * G_DIM + kc * 64 + cc8);
        }
    };

    const int wr = wid >> 3, wc = wid & 7;
    const int arow = lane & 15, acol = (lane >> 4) << 3;
    const int brow = (lane & 7) | ((lane & 16) >> 1), bcol = lane & 8;

    float acc[2][8][4] = {};

    load_chunk(act[0], 0); CP_COMMIT();
    if (nact > 1) { load_chunk(act[1], 1); CP_COMMIT(); }

#pragma unroll 1
    for (int i = 0; i < nact; i++) {
        if (i + 1 < nact) { CP_WAIT(1); } else { CP_WAIT(0); }
        __syncthreads();
        const uint32_t base = sb0 + (uint32_t)((i & 1) * G2_STG) * 2;
#pragma unroll
        for (int kk = 0; kk < 4; kk++) {
            uint32_t af[2][4], bfr[4][4];
#pragma unroll
            for (int mf = 0; mf < 2; mf++)
                ldsm4(af[mf], base + (uint32_t)((wr * 32 + mf * 16 + arow) * G2P +
                                                kk * 16 + acol) * 2);
#pragma unroll
            for (int nh = 0; nh < 4; nh++)
                ldsm4(bfr[nh], base + (uint32_t)((64 + wc * 64 + nh * 16 + brow) * G2P +
                                                 kk * 16 + bcol) * 2);
#pragma unroll
            for (int mf = 0; mf < 2; mf++)
#pragma unroll
                for (int nf = 0; nf < 8; nf++)
                    mma_bf16(acc[mf][nf], af[mf],
                             bfr[nf >> 1][(nf & 1) * 2], bfr[nf >> 1][(nf & 1) * 2 + 1]);
        }
        __syncthreads();
        if (i + 2 < nact) { load_chunk(act[i + 2], i & 1); CP_COMMIT(); }
    }

    // LayerNorm + tanh epilogue (fp32)
    const int ecol = (lane & 3) * 2;
#pragma unroll
    for (int mf = 0; mf < 2; mf++) {
        float s0 = 0.f, q0 = 0.f, s1 = 0.f, q1 = 0.f;
#pragma unroll
        for (int nf = 0; nf < 8; nf++) {
            const int c = wc * 64 + nf * 8 + ecol;
            float v00 = acc[mf][nf][0] + vs_b[c];
            float v01 = acc[mf][nf][1] + vs_b[c + 1];
            float v10 = acc[mf][nf][2] + vs_b[c];
            float v11 = acc[mf][nf][3] + vs_b[c + 1];
            acc[mf][nf][0] = v00; acc[mf][nf][1] = v01;
            acc[mf][nf][2] = v10; acc[mf][nf][3] = v11;
            s0 += v00 + v01; q0 += v00 * v00 + v01 * v01;
            s1 += v10 + v11; q1 += v10 * v10 + v11 * v11;
        }
#pragma unroll
        for (int o = 1; o <= 2; o <<= 1) {
            s0 += __shfl_xor_sync(0xffffffffu, s0, o);
            q0 += __shfl_xor_sync(0xffffffffu, q0, o);
            s1 += __shfl_xor_sync(0xffffffffu, s1, o);
            q1 += __shfl_xor_sync(0xffffffffu, q1, o);
        }
        if ((lane & 3) == 0) {
            const int r0 = wr * 32 + mf * 16 + (lane >> 2);
            part_sum[r0 * 8 + wc] = s0;       part_sq[r0 * 8 + wc] = q0;
            part_sum[(r0 + 8) * 8 + wc] = s1; part_sq[(r0 + 8) * 8 + wc] = q1;
        }
    }
    __syncthreads();
    if (tid < 64) {
        float s = 0.f, q = 0.f;
#pragma unroll
        for (int w = 0; w < 8; w++) { s += part_sum[tid * 8 + w]; q += part_sq[tid * 8 + w]; }
        const float mean = s * (1.0f / 512.0f);
        const float var  = q * (1.0f / 512.0f) - mean * mean;
        stats[tid * 2] = mean;
        stats[tid * 2 + 1] = rsqrtf(var + LN_EPS);
    }
    __syncthreads();

#pragma unroll
    for (int mf = 0; mf < 2; mf++) {
        const int r0 = wr * 32 + mf * 16 + (lane >> 2), r1 = r0 + 8;
        const float m0 = stats[r0 * 2], rs0 = stats[r0 * 2 + 1];
        const float m1 = stats[r1 * 2], rs1 = stats[r1 * 2 + 1];
#pragma unroll
        for (int nf = 0; nf < 8; nf++) {
            const int c = wc * 64 + nf * 8 + ecol;
            const float g0 = vs_g[c], g1 = vs_g[c + 1];
            const float be0 = vs_be[c], be1 = vs_be[c + 1];
            float2 y0 = make_float2(tanhf((acc[mf][nf][0] - m0) * rs0 * g0 + be0),
                                    tanhf((acc[mf][nf][1] - m0) * rs0 * g1 + be1));
            float2 y1 = make_float2(tanhf((acc[mf][nf][2] - m1) * rs1 * g0 + be0),
                                    tanhf((acc[mf][nf][3] - m1) * rs1 * g1 + be1));
            *(float2*)(out + (size_t)(bm + r0) * W_DIM + c) = y0;
            *(float2*)(out + (size_t)(bm + r1) * W_DIM + c) = y1;
        }
    }
}

// ---------------------------------------------------------------------------
extern "C" void kernel_launch(void* const* d_in, const int* in_sizes, int n_in,
                              void* d_out, int out_size) {
    const float* inputs     = (const float*)d_in[0];
    const float* centers    = (const float*)d_in[1];
    const float* log_scales = (const float*)d_in[2];
    const float* W_mix      = (const float*)d_in[3];
    const float* b_mix      = (const float*)d_in[4];
    const float* ln_gamma   = (const float*)d_in[5];
    const float* ln_beta    = (const float*)d_in[6];
    float* out = (float*)d_out;

    cudaFuncSetAttribute(gemm1_rbf, cudaFuncAttributeMaxDynamicSharedMemorySize, G1_SMEM);
    cudaFuncSetAttribute(gemm2_ln,  cudaFuncAttributeMaxDynamicSharedMemorySize, (int)G2_SMEM);

    conv_x<<<B_ROWS / 8, 256>>>(inputs);
    conv_cw<<<128, 256>>>(centers, log_scales, W_mix);
    gemm1_rbf<<<dim3(G_DIM / 128, B_ROWS / 128), 256, G1_SMEM>>>();
    gemm2_ln<<<B_ROWS / 64, 512, G2_SMEM>>>(b_mix, ln_gamma, ln_beta, out);
}

// round 12
// speedup vs baseline: 1.1542x; 1.0376x over previous
#include <cuda_runtime.h>
#include <cuda_bf16.h>
#include <cuda_fp8.h>
#include <math.h>
#include <stdint.h>

#define B_ROWS 65536
#define IN_DIM 256
#define G_DIM  512
#define W_DIM  512
#define LN_EPS 1e-5f

// ---------------- global scratch (device globals; no allocs) ----------------
__device__ uint8_t g_x8[(size_t)B_ROWS * IN_DIM];          // inputs e4m3
__device__ uint8_t g_c8[(size_t)G_DIM * IN_DIM];           // centers e4m3
__device__ __nv_bfloat16 g_wb[(size_t)W_DIM * G_DIM];      // W_mix bf16
__device__ __nv_bfloat16 g_scaled[(size_t)B_ROWS * G_DIM]; // RBF activations bf16
__device__ float g_xsq[B_ROWS];
__device__ float g_csq[G_DIM];
__device__ float g_s[G_DIM];
// nonzero flags: [m-tile of 64 rows][K-chunk of 64 cols] for g_scaled
__device__ int g_nz[(B_ROWS / 64) * 8];

// ---------------- PTX helpers (sm_80/89+ subset; compute_103-safe) ----------
__device__ __forceinline__ uint32_t smem_cast(const void* p) {
    return (uint32_t)__cvta_generic_to_shared(p);
}
__device__ __forceinline__ void cp16(uint32_t dst, const void* src) {
    asm volatile("cp.async.cg.shared.global [%0], [%1], 16;" :: "r"(dst), "l"(src));
}
#define CP_COMMIT() asm volatile("cp.async.commit_group;" ::: "memory")
#define CP_WAIT(n)  asm volatile("cp.async.wait_group %0;" :: "n"(n) : "memory")

__device__ __forceinline__ void ldsm4(uint32_t* r, uint32_t addr) {
    asm volatile("ldmatrix.sync.aligned.m8n8.x4.shared.b16 {%0,%1,%2,%3}, [%4];"
                 : "=r"(r[0]), "=r"(r[1]), "=r"(r[2]), "=r"(r[3]) : "r"(addr));
}
__device__ __forceinline__ void mma_bf16(float* d, const uint32_t* a,
                                         uint32_t b0, uint32_t b1) {
    asm volatile(
        "mma.sync.aligned.m16n8k16.row.col.f32.bf16.bf16.f32 "
        "{%0,%1,%2,%3}, {%4,%5,%6,%7}, {%8,%9}, {%0,%1,%2,%3};"
        : "+f"(d[0]), "+f"(d[1]), "+f"(d[2]), "+f"(d[3])
        : "r"(a[0]), "r"(a[1]), "r"(a[2]), "r"(a[3]), "r"(b0), "r"(b1));
}
__device__ __forceinline__ void mma_fp8(float* d, const uint32_t* a,
                                        uint32_t b0, uint32_t b1) {
    asm volatile(
        "mma.sync.aligned.m16n8k32.row.col.f32.e4m3.e4m3.f32 "
        "{%0,%1,%2,%3}, {%4,%5,%6,%7}, {%8,%9}, {%0,%1,%2,%3};"
        : "+f"(d[0]), "+f"(d[1]), "+f"(d[2]), "+f"(d[3])
        : "r"(a[0]), "r"(a[1]), "r"(a[2]), "r"(a[3]), "r"(b0), "r"(b1));
}

__device__ __forceinline__ ushort4 cvt8_e4m3(float4 a0, float4 a1) {
    ushort4 u;
    u.x = __nv_cvt_float2_to_fp8x2(make_float2(a0.x, a0.y), __NV_SATFINITE, __NV_E4M3);
    u.y = __nv_cvt_float2_to_fp8x2(make_float2(a0.z, a0.w), __NV_SATFINITE, __NV_E4M3);
    u.z = __nv_cvt_float2_to_fp8x2(make_float2(a1.x, a1.y), __NV_SATFINITE, __NV_E4M3);
    u.w = __nv_cvt_float2_to_fp8x2(make_float2(a1.z, a1.w), __NV_SATFINITE, __NV_E4M3);
    return u;
}

// ---------------- merged prep kernel -----------------------------------------
// blocks [0, 8192)      : inputs -> e4m3 + xsq (+ g_nz reset in first 32 blocks)
// blocks [8192, 8256)   : centers -> e4m3 + csq + s
// blocks [8256, 8320)   : W -> bf16
__global__ __launch_bounds__(256) void conv_all(const float* __restrict__ x,
                                                const float* __restrict__ c,
                                                const float* __restrict__ ls,
                                                const float* __restrict__ w) {
    const int lane = threadIdx.x & 31;
    if (blockIdx.x < 8192) {
        const int gtid = blockIdx.x * 256 + threadIdx.x;
        if (gtid < (B_ROWS / 64) * 8) g_nz[gtid] = 0;
        int row = blockIdx.x * 8 + (threadIdx.x >> 5);
        const float* r = x + (size_t)row * IN_DIM;
        int k0 = lane * 8;
        float4 a0 = *(const float4*)(r + k0);
        float4 a1 = *(const float4*)(r + k0 + 4);
        float ss = a0.x*a0.x + a0.y*a0.y + a0.z*a0.z + a0.w*a0.w +
                   a1.x*a1.x + a1.y*a1.y + a1.z*a1.z + a1.w*a1.w;
#pragma unroll
        for (int o = 16; o > 0; o >>= 1) ss += __shfl_xor_sync(0xffffffffu, ss, o);
        if (lane == 0) g_xsq[row] = ss;
        *(ushort4*)(g_x8 + (size_t)row * IN_DIM + k0) = cvt8_e4m3(a0, a1);
    } else if (blockIdx.x < 8256) {
        int g = (blockIdx.x - 8192) * 8 + (threadIdx.x >> 5);
        const float* r = c + (size_t)g * IN_DIM;
        int k0 = lane * 8;
        float4 a0 = *(const float4*)(r + k0);
        float4 a1 = *(const float4*)(r + k0 + 4);
        float ss = a0.x*a0.x + a0.y*a0.y + a0.z*a0.z + a0.w*a0.w +
                   a1.x*a1.x + a1.y*a1.y + a1.z*a1.z + a1.w*a1.w;
#pragma unroll
        for (int o = 16; o > 0; o >>= 1) ss += __shfl_xor_sync(0xffffffffu, ss, o);
        if (lane == 0) { g_csq[g] = ss; g_s[g] = expf(ls[g]); }
        *(ushort4*)(g_c8 + (size_t)g * IN_DIM + k0) = cvt8_e4m3(a0, a1);
    } else {
        int wr = (blockIdx.x - 8256) * 8 + (threadIdx.x >> 5);
        const float* r = w + (size_t)wr * G_DIM;
#pragma unroll
        for (int part = 0; part < 2; part++) {
            int k0 = lane * 16 + part * 8;
            float4 a0 = *(const float4*)(r + k0);
            float4 a1 = *(const float4*)(r + k0 + 4);
            __nv_bfloat162 h0 = __floats2bfloat162_rn(a0.x, a0.y);
            __nv_bfloat162 h1 = __floats2bfloat162_rn(a0.z, a0.w);
            __nv_bfloat162 h2 = __floats2bfloat162_rn(a1.x, a1.y);
            __nv_bfloat162 h3 = __floats2bfloat162_rn(a1.z, a1.w);
            *(uint4*)(g_wb + (size_t)wr * G_DIM + k0) =
                make_uint4(*(uint32_t*)&h0, *(uint32_t*)&h1, *(uint32_t*)&h2, *(uint32_t*)&h3);
        }
    }
}

// ---------------- GEMM1 (RBF, e4m3): 128x128 tile, K=256 resident ------------
#define P1 272
#define G1_B   (128 * P1)
#define G1_SMEM (2 * 128 * P1 + 1024)

__global__ __launch_bounds__(256, 2) void gemm1_rbf() {
    extern __shared__ __align__(16) uint8_t sm[];
    float* s_c0 = (float*)(sm + 2 * 128 * P1);
    float* s_c1 = s_c0 + 128;

    const int tid = threadIdx.x, lane = tid & 31, wid = tid >> 5;
    const int bm = blockIdx.y * 128, bn = blockIdx.x * 128;

    if (tid < 128) { s_c0[tid] = g_csq[bn + tid]; s_c1[tid] = g_s[bn + tid]; }

    const uint32_t sbase = smem_cast(sm);
#pragma unroll
    for (int i = 0; i < 8; i++) {
        const int v = i * 256 + tid;
        const int row = v >> 4, cb = (v & 15) * 16;
        cp16(sbase + (uint32_t)(row * P1 + cb), g_x8 + (size_t)(bm + row) * IN_DIM + cb);
    }
#pragma unroll
    for (int i = 0; i < 8; i++) {
        const int v = i * 256 + tid;
        const int row = v >> 4, cb = (v & 15) * 16;
        cp16(sbase + (uint32_t)(G1_B + row * P1 + cb), g_c8 + (size_t)(bn + row) * IN_DIM + cb);
    }
    CP_COMMIT();
    CP_WAIT(0);
    __syncthreads();

    const int m0 = (wid >> 2) * 64, n0 = (wid & 3) * 32;
    const int arow = lane & 15, acolb = (lane >> 4) * 16;
    const int brow = (lane & 7) | ((lane & 16) >> 1), bcolb = (lane & 8) * 2;

    float acc[4][4][4] = {};
    uint32_t af[2][4][4], bfr[2][2][4];

    auto load_frags = [&](int kk, int b) {
#pragma unroll
        for (int mf = 0; mf < 4; mf++)
            ldsm4(af[b][mf], sbase + (uint32_t)((m0 + mf * 16 + arow) * P1 + kk * 32 + acolb));
#pragma unroll
        for (int nh = 0; nh < 2; nh++)
            ldsm4(bfr[b][nh], sbase + (uint32_t)(G1_B + (n0 + nh * 16 + brow) * P1 + kk * 32 + bcolb));
    };
    auto do_mma = [&](int b) {
#pragma unroll
        for (int mf = 0; mf < 4; mf++)
#pragma unroll
            for (int nf = 0; nf < 4; nf++)
                mma_fp8(acc[mf][nf], af[b][mf],
                        bfr[b][nf >> 1][(nf & 1) * 2], bfr[b][nf >> 1][(nf & 1) * 2 + 1]);
    };

    load_frags(0, 0);
#pragma unroll
    for (int kk = 0; kk < 8; kk++) {
        if (kk < 7) load_frags(kk + 1, (kk + 1) & 1);
        do_mma(kk & 1);
    }

    // epilogue: exp(-(xq+cq-2acc)*s) -> g_scaled bf16 (predicated stores) + flags
    const int erow = lane >> 2, ecol = (lane & 3) * 2;
    uint32_t nzu = 0;
#pragma unroll
    for (int mf = 0; mf < 4; mf++) {
        const int gm0 = bm + m0 + mf * 16 + erow;
        const float xq0 = g_xsq[gm0], xq1 = g_xsq[gm0 + 8];
#pragma unroll
        for (int nf = 0; nf < 4; nf++) {
            const int cl = n0 + nf * 8 + ecol;
            const int gc = bn + cl;
            const float cq0 = s_c0[cl], ss0 = s_c1[cl];
            const float cq1 = s_c0[cl + 1], ss1 = s_c1[cl + 1];
            float v00 = __expf((2.f * acc[mf][nf][0] - xq0 - cq0) * ss0);
            float v01 = __expf((2.f * acc[mf][nf][1] - xq0 - cq1) * ss1);
            float v10 = __expf((2.f * acc[mf][nf][2] - xq1 - cq0) * ss0);
            float v11 = __expf((2.f * acc[mf][nf][3] - xq1 - cq1) * ss1);
            __nv_bfloat162 h0 = __floats2bfloat162_rn(v00, v01);
            __nv_bfloat162 h1 = __floats2bfloat162_rn(v10, v11);
            const uint32_t p0 = *(uint32_t*)&h0, p1 = *(uint32_t*)&h1;
            nzu |= p0 | p1;
            if (p0) *(uint32_t*)(g_scaled + (size_t)gm0 * G_DIM + gc) = p0;
            if (p1) *(uint32_t*)(g_scaled + (size_t)(gm0 + 8) * G_DIM + gc) = p1;
        }
    }
    const uint32_t any = __reduce_or_sync(0xffffffffu, nzu);
    if (lane == 0 && any)
        atomicOr(&g_nz[((bm + m0) >> 6) * 8 + ((bn + n0) >> 6)], 1);
}

// ---------------- GEMM2 + LayerNorm + tanh: persistent, 148 CTAs, 512 thr ----
// Each CTA loops over 64-row tiles. Fast path (tile all-zero): broadcast the
// once-per-CTA LN+tanh(bias) vector with streaming stores. Slow path: single-
// stage block-sparse GEMM + per-row LN (exact for arbitrary inputs).
#define G2P 72
#define G2_STG (576 * G2P)                       // elems: A 64 rows + B 512 rows
#define G2_FLT ((size_t)G2_STG * 2)              // byte offset of float section
#define G2_SMEM (G2_FLT + (512 * 6 + 128 + 32) * 4 + 64)
#define NTILES2 (B_ROWS / 64)

__global__ __launch_bounds__(512, 1) void gemm2_ln(const float* __restrict__ bias,
                                                   const float* __restrict__ gamma,
                                                   const float* __restrict__ beta,
                                                   float* __restrict__ out) {
    extern __shared__ __align__(16) __nv_bfloat16 smh[];
    float* vs_b  = (float*)((char*)smh + G2_FLT);
    float* vs_g  = vs_b + 512;
    float* vs_be = vs_g + 512;
    float* ybuf  = vs_be + 512;      // fast-path result vector (512)
    float* part_sum = ybuf + 512;    // [64 rows][8 col-groups]
    float* part_sq  = part_sum + 512;
    float* stats    = part_sq + 512; // [64][2] mean,rstd
    float* red      = stats + 128;   // 32 floats cross-warp reduce
    int*   s_nz     = (int*)(red + 32);

    const int tid = threadIdx.x, lane = tid & 31, wid = tid >> 5;

    vs_b[tid] = bias[tid]; vs_g[tid] = gamma[tid]; vs_be[tid] = beta[tid];
    __syncthreads();

    // once per CTA: ybuf = tanh(LN(bias))  (thread tid <-> column tid)
    {
        const float v = vs_b[tid];
        float s = v, q = v * v;
#pragma unroll
        for (int o = 16; o > 0; o >>= 1) {
            s += __shfl_xor_sync(0xffffffffu, s, o);
            q += __shfl_xor_sync(0xffffffffu, q, o);
        }
        if (lane == 0) { red[wid] = s; red[wid + 16] = q; }
        __syncthreads();
        if (tid == 0) {
            float ts = 0.f, tq = 0.f;
#pragma unroll
            for (int w = 0; w < 16; w++) { ts += red[w]; tq += red[w + 16]; }
            const float mean = ts * (1.0f / 512.0f);
            const float var  = tq * (1.0f / 512.0f) - mean * mean;
            red[0] = mean;
            red[1] = rsqrtf(var + LN_EPS);
        }
        __syncthreads();
        ybuf[tid] = tanhf((v - red[0]) * red[1] * vs_g[tid] + vs_be[tid]);
    }
    __syncthreads();

    const uint32_t sb0 = smem_cast(smh);
    const int crow = tid >> 3, cc8 = (tid & 7) * 8;
    const int wr = wid >> 3, wc = wid & 7;
    const int arow = lane & 15, acol = (lane >> 4) << 3;
    const int brow = (lane & 7) | ((lane & 16) >> 1), bcol = lane & 8;
    const int ecol = (lane & 3) * 2;

    for (int tile = blockIdx.x; tile < NTILES2; tile += gridDim.x) {
        const int bm = tile * 64;
        if (tid < 8) s_nz[tid] = g_nz[tile * 8 + tid];
        __syncthreads();
        int act[8], nact = 0;
#pragma unroll
        for (int k = 0; k < 8; k++) if (s_nz[k]) act[nact++] = k;
        __syncthreads();   // s_nz consumed before next-iteration overwrite

        // ---------- FAST PATH: broadcast ybuf to 64 rows ----------
        if (nact == 0) {
            const float4* y4 = (const float4*)ybuf;
            float4* o4 = (float4*)(out + (size_t)bm * W_DIM);
#pragma unroll
            for (int i = 0; i < 16; i++) {
                const int idx = tid + i * 512;      // 0..8191
                __stcs(o4 + idx, y4[idx & 127]);    // streaming (write-once)
            }
            continue;
        }

        // ---------- SLOW PATH: single-stage block-sparse GEMM + LN ----------
        float acc[2][8][4] = {};
#pragma unroll 1
        for (int i = 0; i < nact; i++) {
            const int kc = act[i];
            cp16(sb0 + (uint32_t)(crow * G2P + cc8) * 2,
                 g_scaled + (size_t)(bm + crow) * G_DIM + kc * 64 + cc8);
#pragma unroll
            for (int j = 0; j < 8; j++) {
                const int r = crow + j * 64;
                cp16(sb0 + (uint32_t)((64 + r) * G2P + cc8) * 2,
                     g_wb + (size_t)r * G_DIM + kc * 64 + cc8);
            }
            CP_COMMIT();
            CP_WAIT(0);
            __syncthreads();
#pragma unroll
            for (int kk = 0; kk < 4; kk++) {
                uint32_t af[2][4], bfr[4][4];
#pragma unroll
                for (int mf = 0; mf < 2; mf++)
                    ldsm4(af[mf], sb0 + (uint32_t)((wr * 32 + mf * 16 + arow) * G2P +
                                                   kk * 16 + acol) * 2);
#pragma unroll
                for (int nh = 0; nh < 4; nh++)
                    ldsm4(bfr[nh], sb0 + (uint32_t)((64 + wc * 64 + nh * 16 + brow) * G2P +
                                                    kk * 16 + bcol) * 2);
#pragma unroll
                for (int mf = 0; mf < 2; mf++)
#pragma unroll
                    for (int nf = 0; nf < 8; nf++)
                        mma_bf16(acc[mf][nf], af[mf],
                                 bfr[nf >> 1][(nf & 1) * 2], bfr[nf >> 1][(nf & 1) * 2 + 1]);
            }
            __syncthreads();
        }

        // LayerNorm + tanh epilogue (fp32)
#pragma unroll
        for (int mf = 0; mf < 2; mf++) {
            float s0 = 0.f, q0 = 0.f, s1 = 0.f, q1 = 0.f;
#pragma unroll
            for (int nf = 0; nf < 8; nf++) {
                const int c = wc * 64 + nf * 8 + ecol;
                float v00 = acc[mf][nf][0] + vs_b[c];
                float v01 = acc[mf][nf][1] + vs_b[c + 1];
                float v10 = acc[mf][nf][2] + vs_b[c];
                float v11 = acc[mf][nf][3] + vs_b[c + 1];
                acc[mf][nf][0] = v00; acc[mf][nf][1] = v01;
                acc[mf][nf][2] = v10; acc[mf][nf][3] = v11;
                s0 += v00 + v01; q0 += v00 * v00 + v01 * v01;
                s1 += v10 + v11; q1 += v10 * v10 + v11 * v11;
            }
#pragma unroll
            for (int o = 1; o <= 2; o <<= 1) {
                s0 += __shfl_xor_sync(0xffffffffu, s0, o);
                q0 += __shfl_xor_sync(0xffffffffu, q0, o);
                s1 += __shfl_xor_sync(0xffffffffu, s1, o);
                q1 += __shfl_xor_sync(0xffffffffu, q1, o);
            }
            if ((lane & 3) == 0) {
                const int r0 = wr * 32 + mf * 16 + (lane >> 2);
                part_sum[r0 * 8 + wc] = s0;       part_sq[r0 * 8 + wc] = q0;
                part_sum[(r0 + 8) * 8 + wc] = s1; part_sq[(r0 + 8) * 8 + wc] = q1;
            }
        }
        __syncthreads();
        if (tid < 64) {
            float s = 0.f, q = 0.f;
#pragma unroll
            for (int w = 0; w < 8; w++) { s += part_sum[tid * 8 + w]; q += part_sq[tid * 8 + w]; }
            const float mean = s * (1.0f / 512.0f);
            const float var  = q * (1.0f / 512.0f) - mean * mean;
            stats[tid * 2] = mean;
            stats[tid * 2 + 1] = rsqrtf(var + LN_EPS);
        }
        __syncthreads();

#pragma unroll
        for (int mf = 0; mf < 2; mf++) {
            const int r0 = wr * 32 + mf * 16 + (lane >> 2), r1 = r0 + 8;
            const float m0 = stats[r0 * 2], rs0 = stats[r0 * 2 + 1];
            const float m1 = stats[r1 * 2], rs1 = stats[r1 * 2 + 1];
#pragma unroll
            for (int nf = 0; nf < 8; nf++) {
                const int c = wc * 64 + nf * 8 + ecol;
                const float g0 = vs_g[c], g1 = vs_g[c + 1];
                const float be0 = vs_be[c], be1 = vs_be[c + 1];
                float2 y0 = make_float2(tanhf((acc[mf][nf][0] - m0) * rs0 * g0 + be0),
                                        tanhf((acc[mf][nf][1] - m0) * rs0 * g1 + be1));
                float2 y1 = make_float2(tanhf((acc[mf][nf][2] - m1) * rs1 * g0 + be0),
                                        tanhf((acc[mf][nf][3] - m1) * rs1 * g1 + be1));
                *(float2*)(out + (size_t)(bm + r0) * W_DIM + c) = y0;
                *(float2*)(out + (size_t)(bm + r1) * W_DIM + c) = y1;
            }
        }
        __syncthreads();
    }
}

// ---------------------------------------------------------------------------
extern "C" void kernel_launch(void* const* d_in, const int* in_sizes, int n_in,
                              void* d_out, int out_size) {
    const float* inputs     = (const float*)d_in[0];
    const float* centers    = (const float*)d_in[1];
    const float* log_scales = (const float*)d_in[2];
    const float* W_mix      = (const float*)d_in[3];
    const float* b_mix      = (const float*)d_in[4];
    const float* ln_gamma   = (const float*)d_in[5];
    const float* ln_beta    = (const float*)d_in[6];
    float* out = (float*)d_out;

    cudaFuncSetAttribute(gemm1_rbf, cudaFuncAttributeMaxDynamicSharedMemorySize, G1_SMEM);
    cudaFuncSetAttribute(gemm2_ln,  cudaFuncAttributeMaxDynamicSharedMemorySize, (int)G2_SMEM);

    conv_all<<<8320, 256>>>(inputs, centers, log_scales, W_mix);
    gemm1_rbf<<<dim3(G_DIM / 128, B_ROWS / 128), 256, G1_SMEM>>>();
    gemm2_ln<<<148, 512, G2_SMEM>>>(b_mix, ln_gamma, ln_beta, out);
}